// round 5
// baseline (speedup 1.0000x reference)
#include <cuda_runtime.h>
#include <cuda_bf16.h>
#include <math.h>
#include <stdint.h>

// ---------------------------------------------------------------------------
// Round 5: bf16x3 tensor-core fused NeRF, N-split warp pairs.
// Block = 512 threads (16 warps), tile = 128 points, TPB tiles per block.
// Warp 2g+h: rows [16g,16g+16), output cols [32h, 32h+32). __syncthreads
// between layers. Same smem footprint as R4 -> 16 warps/SM (occ 25%).
// ---------------------------------------------------------------------------

#define LVLS 24
#define TSZ  (1u << 19)
#define P1   2654435761u
#define P2   805459861u

#define XW        84
#define TILE_PTS  128
#define TPB       8
#define NTHREADS  512

#define WPLANE 26400
#define WOFF_L0 0
#define WOFF_L1 3200
#define WOFF_L2 7424
#define WOFF_L3 11648
#define WOFF_R0 16400
#define WOFF_R1 21648
#define WOFF_R2 25872

#define BOFF_L0 0
#define BOFF_L1 64
#define BOFF_L2 128
#define BOFF_L3 192
#define BOFF_R0 264
#define BOFF_R1 328
#define BOFF_R2 392
#define BIAS_FLOATS 400

#define SO_WHI  0
#define SO_WLO  (WPLANE * 2)
#define SO_BIAS (WPLANE * 4)
#define SO_XAHI (SO_BIAS + BIAS_FLOATS * 4)
#define XPLANE_B (TILE_PTS * XW * 2)
#define SO_XALO (SO_XAHI + XPLANE_B)
#define SO_XBHI (SO_XALO + XPLANE_B)
#define SO_XBLO (SO_XBHI + XPLANE_B)
#define SMEM_BYTES (SO_XBLO + XPLANE_B)

struct ResArr { float r[LVLS]; };
struct WPtrs  { const float* w[14]; };

typedef unsigned short u16;
typedef unsigned int   u32;

__device__ __forceinline__ float gelu_exact(float x) {
    return 0.5f * x * (1.0f + erff(x * 0.70710678118654752440f));
}
__device__ __forceinline__ float softplus_f(float x) {
    return fmaxf(x, 0.0f) + log1pf(expf(-fabsf(x)));
}
__device__ __forceinline__ float sigmoid_f(float x) {
    return 1.0f / (1.0f + expf(-x));
}

#define MMA_BF16(d, a0, a1, a2, a3, b0, b1)                                   \
    asm volatile(                                                             \
        "mma.sync.aligned.m16n8k16.row.col.f32.bf16.bf16.f32 "                \
        "{%0,%1,%2,%3}, {%4,%5,%6,%7}, {%8,%9}, {%0,%1,%2,%3};"               \
        : "+f"(d[0]), "+f"(d[1]), "+f"(d[2]), "+f"(d[3])                      \
        : "r"(a0), "r"(a1), "r"(a2), "r"(a3), "r"(b0), "r"(b1))

__device__ __forceinline__ void bf16_split(float v, u16& hi, u16& lo) {
    __nv_bfloat16 h = __float2bfloat16_rn(v);
    float r = v - __bfloat162float(h);
    __nv_bfloat16 l = __float2bfloat16_rn(r);
    hi = __bfloat16_as_ushort(h);
    lo = __bfloat16_as_ushort(l);
}

__device__ __forceinline__ void split_store2(u16* phi, u16* plo,
                                             float v0, float v1) {
    u16 h0, l0, h1, l1;
    bf16_split(v0, h0, l0);
    bf16_split(v1, h1, l1);
    *(u32*)phi = (u32)h0 | ((u32)h1 << 16);
    *(u32*)plo = (u32)l0 | ((u32)l1 << 16);
}

__device__ __forceinline__ void split_store1(u16* phi, u16* plo, float v) {
    u16 h, l;
    bf16_split(v, h, l);
    *phi = h;
    *plo = l;
}

// one dense layer slice: 16 rows (xhi/xlo at warp row base),
// output cols [NTB*8, (NTB+NT)*8)
template<int KT, int NT, int KP, int NTB>
__device__ __forceinline__ void run_layer(const u16* __restrict__ xhi,
                                          const u16* __restrict__ xlo,
                                          const u16* __restrict__ whi,
                                          const u16* __restrict__ wlo,
                                          const float* __restrict__ bias,
                                          float (&acc)[NT][4], int lane)
{
    const int qr = lane >> 2, qm = lane & 3;
#pragma unroll
    for (int nt = 0; nt < NT; nt++) {
        float b0 = bias[(NTB + nt) * 8 + 2 * qm];
        float b1 = bias[(NTB + nt) * 8 + 2 * qm + 1];
        acc[nt][0] = b0; acc[nt][1] = b1;
        acc[nt][2] = b0; acc[nt][3] = b1;
    }
    const u16* pa  = xhi + qr * XW + 2 * qm;
    const u16* pal = xlo + qr * XW + 2 * qm;
#pragma unroll
    for (int kt = 0; kt < KT; kt++) {
        u32 ah0 = *(const u32*)(pa  + kt * 16);
        u32 ah1 = *(const u32*)(pa  + kt * 16 + 8 * XW);
        u32 ah2 = *(const u32*)(pa  + kt * 16 + 8);
        u32 ah3 = *(const u32*)(pa  + kt * 16 + 8 * XW + 8);
        u32 al0 = *(const u32*)(pal + kt * 16);
        u32 al1 = *(const u32*)(pal + kt * 16 + 8 * XW);
        u32 al2 = *(const u32*)(pal + kt * 16 + 8);
        u32 al3 = *(const u32*)(pal + kt * 16 + 8 * XW + 8);
#pragma unroll
        for (int nt = 0; nt < NT; nt++) {
            const u16* pb  = whi + ((NTB + nt) * 8 + qr) * KP + 2 * qm + kt * 16;
            const u16* pbl = wlo + ((NTB + nt) * 8 + qr) * KP + 2 * qm + kt * 16;
            u32 bh0 = *(const u32*)(pb);
            u32 bh1 = *(const u32*)(pb + 8);
            u32 bl0 = *(const u32*)(pbl);
            u32 bl1 = *(const u32*)(pbl + 8);
            MMA_BF16(acc[nt], ah0, ah1, ah2, ah3, bh0, bh1);
            MMA_BF16(acc[nt], ah0, ah1, ah2, ah3, bl0, bl1);
            MMA_BF16(acc[nt], al0, al1, al2, al3, bh0, bh1);
        }
    }
}

template<int NT, int NTB>
__device__ __forceinline__ void store_acts_gelu(u16* __restrict__ yhi,
                                                u16* __restrict__ ylo,
                                                float (&acc)[NT][4], int lane)
{
    const int qr = lane >> 2, qm = lane & 3;
#pragma unroll
    for (int nt = 0; nt < NT; nt++) {
        int c = (NTB + nt) * 8 + 2 * qm;
        split_store2(yhi + qr * XW + c,       ylo + qr * XW + c,
                     gelu_exact(acc[nt][0]),  gelu_exact(acc[nt][1]));
        split_store2(yhi + (qr + 8) * XW + c, ylo + (qr + 8) * XW + c,
                     gelu_exact(acc[nt][2]),  gelu_exact(acc[nt][3]));
    }
}

__device__ void stage_w(const float* __restrict__ g, u16* hi, u16* lo,
                        int realK, int realN, int K, int NPAD, int KP, int tid)
{
    for (int idx = tid; idx < NPAD * K; idx += NTHREADS) {
        int nn = idx / K, kk = idx % K;
        float v = (kk < realK && nn < realN) ? g[kk * realN + nn] : 0.0f;
        u16 h, l;
        bf16_split(v, h, l);
        hi[nn * KP + kk] = h;
        lo[nn * KP + kk] = l;
    }
}
__device__ void stage_b(const float* __restrict__ g, float* dst,
                        int realN, int NPAD, int tid)
{
    for (int i = tid; i < NPAD; i += NTHREADS)
        dst[i] = (i < realN) ? g[i] : 0.0f;
}

__global__ void __launch_bounds__(NTHREADS, 1)
nerf_tc_kernel(const float* __restrict__ pts,
               const float* __restrict__ dirs,
               const float* __restrict__ table,
               WPtrs prm, ResArr res,
               float* __restrict__ out, int n)
{
    extern __shared__ char smem[];
    u16*   whi  = (u16*)(smem + SO_WHI);
    u16*   wlo  = (u16*)(smem + SO_WLO);
    float* bias = (float*)(smem + SO_BIAS);
    u16*   xahi = (u16*)(smem + SO_XAHI);
    u16*   xalo = (u16*)(smem + SO_XALO);
    u16*   xbhi = (u16*)(smem + SO_XBHI);
    u16*   xblo = (u16*)(smem + SO_XBLO);

    const int tid  = threadIdx.x;
    const int warp = tid >> 5;
    const int lane = tid & 31;
    const int qr = lane >> 2, qm = lane & 3;
    const int rg    = warp >> 1;   // row-group 0..7
    const int nhalf = warp & 1;    // 0: cols 0..31, 1: cols 32..63

    // ---- stage weights/biases ----
    stage_w(prm.w[0],  whi + WOFF_L0, wlo + WOFF_L0, 48, 64, 48, 64, 50, tid);
    stage_w(prm.w[2],  whi + WOFF_L1, wlo + WOFF_L1, 64, 64, 64, 64, 66, tid);
    stage_w(prm.w[4],  whi + WOFF_L2, wlo + WOFF_L2, 64, 64, 64, 64, 66, tid);
    stage_w(prm.w[6],  whi + WOFF_L3, wlo + WOFF_L3, 64, 65, 64, 72, 66, tid);
    stage_w(prm.w[8],  whi + WOFF_R0, wlo + WOFF_R0, 73, 64, 80, 64, 82, tid);
    stage_w(prm.w[10], whi + WOFF_R1, wlo + WOFF_R1, 64, 64, 64, 64, 66, tid);
    stage_w(prm.w[12], whi + WOFF_R2, wlo + WOFF_R2, 64,  3, 64,  8, 66, tid);
    stage_b(prm.w[1],  bias + BOFF_L0, 64, 64, tid);
    stage_b(prm.w[3],  bias + BOFF_L1, 64, 64, tid);
    stage_b(prm.w[5],  bias + BOFF_L2, 64, 64, tid);
    stage_b(prm.w[7],  bias + BOFF_L3, 65, 72, tid);
    stage_b(prm.w[9],  bias + BOFF_R0, 64, 64, tid);
    stage_b(prm.w[11], bias + BOFF_R1, 64, 64, tid);
    stage_b(prm.w[13], bias + BOFF_R2,  3,  8, tid);

    // zero XA pad cols 73..83 (R0 reads K up to 79; stays zero across tiles)
    for (int idx = tid; idx < TILE_PTS * 11; idx += NTHREADS) {
        int r = idx / 11, c = 73 + idx % 11;
        xahi[r * XW + c] = 0;
        xalo[r * XW + c] = 0;
    }
    __syncthreads();

    u16* Ahi = xahi + rg * 16 * XW;
    u16* Alo = xalo + rg * 16 * XW;
    u16* Bhi = xbhi + rg * 16 * XW;
    u16* Blo = xblo + rg * 16 * XW;

    for (int t = 0; t < TPB; t++) {
        const int base = (blockIdx.x * TPB + t) * TILE_PTS;

        // ---- hash gather: 4 threads per point, 6 levels each ----
        {
            const int plocal = tid >> 2;          // 0..127
            const int gpt = base + plocal;
            float px = pts[gpt * 3 + 0];
            float py = pts[gpt * 3 + 1];
            float pz = pts[gpt * 3 + 2];
            float x0 = (px + 1.0f) * 0.5f;
            float y0 = (py + 1.0f) * 0.5f;
            float z0 = (pz + 1.0f) * 0.5f;
            const int l0 = (tid & 3) * 6;
#pragma unroll 1
            for (int l = l0; l < l0 + 6; l++) {
                float rl = res.r[l];
                float posx = x0 * rl, posy = y0 * rl, posz = z0 * rl;
                float fx = floorf(posx), fy = floorf(posy), fz = floorf(posz);
                float wx = posx - fx, wy = posy - fy, wz = posz - fz;
                unsigned ux = (unsigned)fx, uy = (unsigned)fy, uz = (unsigned)fz;
                unsigned hX[2] = {ux, ux + 1u};
                unsigned hY[2] = {uy * P1, (uy + 1u) * P1};
                unsigned hZ[2] = {uz * P2, (uz + 1u) * P2};
                float wX[2] = {1.0f - wx, wx};
                float wY[2] = {1.0f - wy, wy};
                float wZ[2] = {1.0f - wz, wz};
                const float2* tb = (const float2*)table + (size_t)l * TSZ;
                float2 f[8]; float wt[8];
#pragma unroll
                for (int c = 0; c < 8; c++) {
                    int bx = (c >> 2) & 1, by = (c >> 1) & 1, bz = c & 1;
                    unsigned idx = (hX[bx] ^ hY[by] ^ hZ[bz]) & (TSZ - 1u);
                    f[c]  = __ldg(tb + idx);
                    wt[c] = wX[bx] * wY[by] * wZ[bz];
                }
                float a0 = 0.0f, a1 = 0.0f;
#pragma unroll
                for (int c = 0; c < 8; c++) {
                    a0 = fmaf(f[c].x, wt[c], a0);
                    a1 = fmaf(f[c].y, wt[c], a1);
                }
                split_store2(xahi + plocal * XW + 2 * l,
                             xalo + plocal * XW + 2 * l, a0, a1);
            }
        }
        __syncthreads();

        // ---- feature MLP ----
        if (nhalf == 0) {
            float acc[4][4];
            run_layer<3, 4, 50, 0>(Ahi, Alo, whi + WOFF_L0, wlo + WOFF_L0,
                                   bias + BOFF_L0, acc, lane);
            store_acts_gelu<4, 0>(Bhi, Blo, acc, lane);
        } else {
            float acc[4][4];
            run_layer<3, 4, 50, 4>(Ahi, Alo, whi + WOFF_L0, wlo + WOFF_L0,
                                   bias + BOFF_L0, acc, lane);
            store_acts_gelu<4, 4>(Bhi, Blo, acc, lane);
        }
        __syncthreads();
        if (nhalf == 0) {
            float acc[4][4];
            run_layer<4, 4, 66, 0>(Bhi, Blo, whi + WOFF_L1, wlo + WOFF_L1,
                                   bias + BOFF_L1, acc, lane);
            store_acts_gelu<4, 0>(Ahi, Alo, acc, lane);
        } else {
            float acc[4][4];
            run_layer<4, 4, 66, 4>(Bhi, Blo, whi + WOFF_L1, wlo + WOFF_L1,
                                   bias + BOFF_L1, acc, lane);
            store_acts_gelu<4, 4>(Ahi, Alo, acc, lane);
        }
        __syncthreads();
        if (nhalf == 0) {
            float acc[4][4];
            run_layer<4, 4, 66, 0>(Ahi, Alo, whi + WOFF_L2, wlo + WOFF_L2,
                                   bias + BOFF_L2, acc, lane);
            store_acts_gelu<4, 0>(Bhi, Blo, acc, lane);
        } else {
            float acc[4][4];
            run_layer<4, 4, 66, 4>(Ahi, Alo, whi + WOFF_L2, wlo + WOFF_L2,
                                   bias + BOFF_L2, acc, lane);
            store_acts_gelu<4, 4>(Bhi, Blo, acc, lane);
        }
        __syncthreads();

        // ---- L3 (N=65 padded 72): warp0 nt 0..4, warp1 nt 5..8 ----
        if (nhalf == 0) {
            float acc[5][4];
            run_layer<4, 5, 66, 0>(Bhi, Blo, whi + WOFF_L3, wlo + WOFF_L3,
                                   bias + BOFF_L3, acc, lane);
#pragma unroll
            for (int nt = 0; nt < 5; nt++) {
#pragma unroll
                for (int j = 0; j < 4; j++) {
                    int col  = nt * 8 + 2 * qm + (j & 1);
                    int lrow = qr + ((j >> 1) ? 8 : 0);
                    float v = acc[nt][j];
                    if (col == 0) {
                        out[(size_t)3 * n + (base + rg * 16 + lrow)] =
                            softplus_f(v);
                    } else {
                        float g = gelu_exact(v);
                        split_store1(Ahi + lrow * XW + (col - 1),
                                     Alo + lrow * XW + (col - 1), g);
                    }
                }
            }
        } else {
            float acc[4][4];
            run_layer<4, 4, 66, 5>(Bhi, Blo, whi + WOFF_L3, wlo + WOFF_L3,
                                   bias + BOFF_L3, acc, lane);
#pragma unroll
            for (int nt = 0; nt < 4; nt++) {
#pragma unroll
                for (int j = 0; j < 4; j++) {
                    int col  = (5 + nt) * 8 + 2 * qm + (j & 1);
                    int lrow = qr + ((j >> 1) ? 8 : 0);
                    if (col <= 64) {
                        float g = gelu_exact(acc[nt][j]);
                        split_store1(Ahi + lrow * XW + (col - 1),
                                     Alo + lrow * XW + (col - 1), g);
                    }
                }
            }
        }
        // SH -> XA cols 64..72 (nhalf==0 warps, lanes 0..15)
        if (nhalf == 0 && lane < 16) {
            int lrow = lane;
            int gpt = base + rg * 16 + lrow;
            float dx = dirs[gpt * 3 + 0];
            float dy = dirs[gpt * 3 + 1];
            float dz = dirs[gpt * 3 + 2];
            float sh[9];
            sh[0] = 0.28209479177387814f;
            sh[1] = -0.48860251190291987f * dy;
            sh[2] =  0.48860251190291987f * dz;
            sh[3] = -0.48860251190291987f * dx;
            sh[4] =  1.0925484305920792f  * dx * dy;
            sh[5] = -1.0925484305920792f  * dy * dz;
            sh[6] =  0.31539156525252005f * (3.0f * dz * dz - 1.0f);
            sh[7] = -1.0925484305920792f  * dx * dz;
            sh[8] =  0.5462742152960396f  * (dx * dx - dy * dy);
#pragma unroll
            for (int j = 0; j < 9; j++)
                split_store1(Ahi + lrow * XW + 64 + j,
                             Alo + lrow * XW + 64 + j, sh[j]);
        }
        __syncthreads();

        // ---- RGB MLP ----
        if (nhalf == 0) {
            float acc[4][4];
            run_layer<5, 4, 82, 0>(Ahi, Alo, whi + WOFF_R0, wlo + WOFF_R0,
                                   bias + BOFF_R0, acc, lane);
            store_acts_gelu<4, 0>(Bhi, Blo, acc, lane);
        } else {
            float acc[4][4];
            run_layer<5, 4, 82, 4>(Ahi, Alo, whi + WOFF_R0, wlo + WOFF_R0,
                                   bias + BOFF_R0, acc, lane);
            store_acts_gelu<4, 4>(Bhi, Blo, acc, lane);
        }
        __syncthreads();
        if (nhalf == 0) {
            float acc[4][4];
            run_layer<4, 4, 66, 0>(Bhi, Blo, whi + WOFF_R1, wlo + WOFF_R1,
                                   bias + BOFF_R1, acc, lane);
            store_acts_gelu<4, 0>(Ahi, Alo, acc, lane);
        } else {
            float acc[4][4];
            run_layer<4, 4, 66, 4>(Bhi, Blo, whi + WOFF_R1, wlo + WOFF_R1,
                                   bias + BOFF_R1, acc, lane);
            store_acts_gelu<4, 4>(Ahi, Alo, acc, lane);
        }
        __syncthreads();
        if (nhalf == 0) {
            float acc[1][4];
            run_layer<4, 1, 66, 0>(Ahi, Alo, whi + WOFF_R2, wlo + WOFF_R2,
                                   bias + BOFF_R2, acc, lane);
            int pt0 = base + rg * 16 + qr;
            int pt1 = pt0 + 8;
            if (qm == 0) {
                out[pt0 * 3 + 0] = sigmoid_f(acc[0][0]);
                out[pt0 * 3 + 1] = sigmoid_f(acc[0][1]);
                out[pt1 * 3 + 0] = sigmoid_f(acc[0][2]);
                out[pt1 * 3 + 1] = sigmoid_f(acc[0][3]);
            } else if (qm == 1) {
                out[pt0 * 3 + 2] = sigmoid_f(acc[0][0]);
                out[pt1 * 3 + 2] = sigmoid_f(acc[0][2]);
            }
        }
        __syncthreads();
    }
}

extern "C" void kernel_launch(void* const* d_in, const int* in_sizes, int n_in,
                              void* d_out, int out_size)
{
    const float* pts   = (const float*)d_in[0];
    const float* dirs  = (const float*)d_in[1];
    const float* table = (const float*)d_in[2];

    WPtrs prm;
    for (int a = 0; a < 14; a++) prm.w[a] = (const float*)d_in[3 + a];

    int n = in_sizes[0] / 3;

    ResArr res;
    double b = exp((log(2048.0) - log(16.0)) / 23.0);
    for (int l = 0; l < LVLS; l++)
        res.r[l] = (float)floor(16.0 * pow(b, (double)l));

    cudaFuncSetAttribute(nerf_tc_kernel,
                         cudaFuncAttributeMaxDynamicSharedMemorySize, SMEM_BYTES);

    int ntiles = n / TILE_PTS;             // 4096
    int blocks = ntiles / TPB;             // 512
    nerf_tc_kernel<<<blocks, NTHREADS, SMEM_BYTES>>>(
        pts, dirs, table, prm, res, (float*)d_out, n);
}

// round 6
// speedup vs baseline: 1.3610x; 1.3610x over previous
#include <cuda_runtime.h>
#include <cuda_bf16.h>
#include <math.h>
#include <stdint.h>

// ---------------------------------------------------------------------------
// Round 6: R4 dataflow (warp-independent, __syncwarp only) +
//  (a) software-pipelined hash gather (tile t+1 gathered during tile t MLP)
//  (b) conflict-free smem strides (all strides == 8 mod 16 u16)
// Block = 256 threads (8 warps). Warp owns 16 points end-to-end.
// bf16 hi/lo 3-term mma.sync.m16n8k16, fp32 accum.
// ---------------------------------------------------------------------------

#define LVLS 24
#define TSZ  (1u << 19)
#define P1   2654435761u
#define P2   805459861u

#define TILE_PTS  128
#define TPB       4
#define NTHREADS  256

#define CW   56
#define XBW  72
#define XAW  88

#define WPLANE  28800
#define WOFF_L0 0
#define WOFF_L1 3584
#define WOFF_L2 8192
#define WOFF_L3 12800
#define WOFF_R0 17984
#define WOFF_R1 23616
#define WOFF_R2 28224

#define BOFF_L0 0
#define BOFF_L1 64
#define BOFF_L2 128
#define BOFF_L3 192
#define BOFF_R0 264
#define BOFF_R1 328
#define BOFF_R2 392
#define BIAS_FLOATS 400

#define SO_WHI  0
#define SO_WLO  57600
#define SO_BIAS 115200
#define SO_XAHI 116800
#define SO_XALO 139328
#define SO_XBHI 161856
#define SO_XBLO 180288
#define SO_CHI  198720
#define SO_CLO  213056
#define SMEM_BYTES 227392

struct ResArr { float r[LVLS]; };
struct WPtrs  { const float* w[14]; };

typedef unsigned short u16;
typedef unsigned int   u32;

__device__ __forceinline__ float gelu_exact(float x) {
    return 0.5f * x * (1.0f + erff(x * 0.70710678118654752440f));
}
__device__ __forceinline__ float softplus_f(float x) {
    return fmaxf(x, 0.0f) + log1pf(expf(-fabsf(x)));
}
__device__ __forceinline__ float sigmoid_f(float x) {
    return 1.0f / (1.0f + expf(-x));
}

#define MMA_BF16(d, a0, a1, a2, a3, b0, b1)                                   \
    asm volatile(                                                             \
        "mma.sync.aligned.m16n8k16.row.col.f32.bf16.bf16.f32 "                \
        "{%0,%1,%2,%3}, {%4,%5,%6,%7}, {%8,%9}, {%0,%1,%2,%3};"               \
        : "+f"(d[0]), "+f"(d[1]), "+f"(d[2]), "+f"(d[3])                      \
        : "r"(a0), "r"(a1), "r"(a2), "r"(a3), "r"(b0), "r"(b1))

__device__ __forceinline__ void bf16_split(float v, u16& hi, u16& lo) {
    __nv_bfloat16 h = __float2bfloat16_rn(v);
    float r = v - __bfloat162float(h);
    __nv_bfloat16 l = __float2bfloat16_rn(r);
    hi = __bfloat16_as_ushort(h);
    lo = __bfloat16_as_ushort(l);
}

__device__ __forceinline__ void split_store2(u16* phi, u16* plo,
                                             float v0, float v1) {
    u16 h0, l0, h1, l1;
    bf16_split(v0, h0, l0);
    bf16_split(v1, h1, l1);
    *(u32*)phi = (u32)h0 | ((u32)h1 << 16);
    *(u32*)plo = (u32)l0 | ((u32)l1 << 16);
}

__device__ __forceinline__ void split_store1(u16* phi, u16* plo, float v) {
    u16 h, l;
    bf16_split(v, h, l);
    *phi = h;
    *plo = l;
}

template<int KT, int NT, int KP, int XS>
__device__ __forceinline__ void run_layer(const u16* __restrict__ xhi,
                                          const u16* __restrict__ xlo,
                                          const u16* __restrict__ whi,
                                          const u16* __restrict__ wlo,
                                          const float* __restrict__ bias,
                                          float (&acc)[NT][4], int lane)
{
    const int qr = lane >> 2, qm = lane & 3;
#pragma unroll
    for (int nt = 0; nt < NT; nt++) {
        float b0 = bias[nt * 8 + 2 * qm];
        float b1 = bias[nt * 8 + 2 * qm + 1];
        acc[nt][0] = b0; acc[nt][1] = b1;
        acc[nt][2] = b0; acc[nt][3] = b1;
    }
    const u16* pa  = xhi + qr * XS + 2 * qm;
    const u16* pal = xlo + qr * XS + 2 * qm;
#pragma unroll
    for (int kt = 0; kt < KT; kt++) {
        u32 ah0 = *(const u32*)(pa  + kt * 16);
        u32 ah1 = *(const u32*)(pa  + kt * 16 + 8 * XS);
        u32 ah2 = *(const u32*)(pa  + kt * 16 + 8);
        u32 ah3 = *(const u32*)(pa  + kt * 16 + 8 * XS + 8);
        u32 al0 = *(const u32*)(pal + kt * 16);
        u32 al1 = *(const u32*)(pal + kt * 16 + 8 * XS);
        u32 al2 = *(const u32*)(pal + kt * 16 + 8);
        u32 al3 = *(const u32*)(pal + kt * 16 + 8 * XS + 8);
#pragma unroll
        for (int nt = 0; nt < NT; nt++) {
            const u16* pb  = whi + (nt * 8 + qr) * KP + 2 * qm + kt * 16;
            const u16* pbl = wlo + (nt * 8 + qr) * KP + 2 * qm + kt * 16;
            u32 bh0 = *(const u32*)(pb);
            u32 bh1 = *(const u32*)(pb + 8);
            u32 bl0 = *(const u32*)(pbl);
            u32 bl1 = *(const u32*)(pbl + 8);
            MMA_BF16(acc[nt], ah0, ah1, ah2, ah3, bh0, bh1);
            MMA_BF16(acc[nt], ah0, ah1, ah2, ah3, bl0, bl1);
            MMA_BF16(acc[nt], al0, al1, al2, al3, bh0, bh1);
        }
    }
}

template<int NT, int YS>
__device__ __forceinline__ void store_acts_gelu(u16* __restrict__ yhi,
                                                u16* __restrict__ ylo,
                                                float (&acc)[NT][4], int lane)
{
    const int qr = lane >> 2, qm = lane & 3;
#pragma unroll
    for (int nt = 0; nt < NT; nt++) {
        int c = nt * 8 + 2 * qm;
        split_store2(yhi + qr * YS + c,       ylo + qr * YS + c,
                     gelu_exact(acc[nt][0]),  gelu_exact(acc[nt][1]));
        split_store2(yhi + (qr + 8) * YS + c, ylo + (qr + 8) * YS + c,
                     gelu_exact(acc[nt][2]),  gelu_exact(acc[nt][3]));
    }
}

__device__ __forceinline__ void gather_issue(const float* __restrict__ table,
                                             float rl, float x0, float y0,
                                             float z0, int l,
                                             float2 (&f)[8], float (&wt)[8])
{
    float posx = x0 * rl, posy = y0 * rl, posz = z0 * rl;
    float fx = floorf(posx), fy = floorf(posy), fz = floorf(posz);
    float wx = posx - fx, wy = posy - fy, wz = posz - fz;
    unsigned ux = (unsigned)fx, uy = (unsigned)fy, uz = (unsigned)fz;
    unsigned hX[2] = {ux, ux + 1u};
    unsigned hY[2] = {uy * P1, (uy + 1u) * P1};
    unsigned hZ[2] = {uz * P2, (uz + 1u) * P2};
    float wX[2] = {1.0f - wx, wx};
    float wY[2] = {1.0f - wy, wy};
    float wZ[2] = {1.0f - wz, wz};
    const float2* tb = (const float2*)table + (size_t)l * TSZ;
#pragma unroll
    for (int c = 0; c < 8; c++) {
        int bx = (c >> 2) & 1, by = (c >> 1) & 1, bz = c & 1;
        unsigned idx = (hX[bx] ^ hY[by] ^ hZ[bz]) & (TSZ - 1u);
        f[c]  = __ldg(tb + idx);
        wt[c] = wX[bx] * wY[by] * wZ[bz];
    }
}

__device__ __forceinline__ void gather_consume(u16* __restrict__ chi,
                                               u16* __restrict__ clo,
                                               int row, int l,
                                               float2 (&f)[8], float (&wt)[8])
{
    float a0 = 0.0f, a1 = 0.0f;
#pragma unroll
    for (int c = 0; c < 8; c++) {
        a0 = fmaf(f[c].x, wt[c], a0);
        a1 = fmaf(f[c].y, wt[c], a1);
    }
    split_store2(chi + row * CW + 2 * l, clo + row * CW + 2 * l, a0, a1);
}

__device__ void stage_w(const float* __restrict__ g, u16* hi, u16* lo,
                        int realK, int realN, int K, int NPAD, int KP, int tid)
{
    for (int idx = tid; idx < NPAD * K; idx += NTHREADS) {
        int nn = idx / K, kk = idx % K;
        float v = (kk < realK && nn < realN) ? g[kk * realN + nn] : 0.0f;
        u16 h, l;
        bf16_split(v, h, l);
        hi[nn * KP + kk] = h;
        lo[nn * KP + kk] = l;
    }
}
__device__ void stage_b(const float* __restrict__ g, float* dst,
                        int realN, int NPAD, int tid)
{
    for (int i = tid; i < NPAD; i += NTHREADS)
        dst[i] = (i < realN) ? g[i] : 0.0f;
}

__global__ void __launch_bounds__(NTHREADS, 1)
nerf_tc_kernel(const float* __restrict__ pts,
               const float* __restrict__ dirs,
               const float* __restrict__ table,
               WPtrs prm, ResArr res,
               float* __restrict__ out, int n)
{
    extern __shared__ char smem[];
    u16*   whi  = (u16*)(smem + SO_WHI);
    u16*   wlo  = (u16*)(smem + SO_WLO);
    float* bias = (float*)(smem + SO_BIAS);
    u16*   xahi = (u16*)(smem + SO_XAHI);
    u16*   xalo = (u16*)(smem + SO_XALO);
    u16*   xbhi = (u16*)(smem + SO_XBHI);
    u16*   xblo = (u16*)(smem + SO_XBLO);
    u16*   chi  = (u16*)(smem + SO_CHI);
    u16*   clo  = (u16*)(smem + SO_CLO);

    const int tid  = threadIdx.x;
    const int warp = tid >> 5;
    const int lane = tid & 31;
    const int qr = lane >> 2, qm = lane & 3;
    const int rg = warp;

    stage_w(prm.w[0],  whi + WOFF_L0, wlo + WOFF_L0, 48, 64, 48, 64, 56, tid);
    stage_w(prm.w[2],  whi + WOFF_L1, wlo + WOFF_L1, 64, 64, 64, 64, 72, tid);
    stage_w(prm.w[4],  whi + WOFF_L2, wlo + WOFF_L2, 64, 64, 64, 64, 72, tid);
    stage_w(prm.w[6],  whi + WOFF_L3, wlo + WOFF_L3, 64, 65, 64, 72, 72, tid);
    stage_w(prm.w[8],  whi + WOFF_R0, wlo + WOFF_R0, 73, 64, 80, 64, 88, tid);
    stage_w(prm.w[10], whi + WOFF_R1, wlo + WOFF_R1, 64, 64, 64, 64, 72, tid);
    stage_w(prm.w[12], whi + WOFF_R2, wlo + WOFF_R2, 64,  3, 64,  8, 72, tid);
    stage_b(prm.w[1],  bias + BOFF_L0, 64, 64, tid);
    stage_b(prm.w[3],  bias + BOFF_L1, 64, 64, tid);
    stage_b(prm.w[5],  bias + BOFF_L2, 64, 64, tid);
    stage_b(prm.w[7],  bias + BOFF_L3, 65, 72, tid);
    stage_b(prm.w[9],  bias + BOFF_R0, 64, 64, tid);
    stage_b(prm.w[11], bias + BOFF_R1, 64, 64, tid);
    stage_b(prm.w[13], bias + BOFF_R2,  3,  8, tid);

    for (int idx = tid; idx < TILE_PTS * 7; idx += NTHREADS) {
        int r = idx / 7, c = 73 + idx % 7;
        xahi[r * XAW + c] = 0;
        xalo[r * XAW + c] = 0;
    }
    __syncthreads();

    u16* Ahi = xahi + rg * 16 * XAW;
    u16* Alo = xalo + rg * 16 * XAW;
    u16* Bhi = xbhi + rg * 16 * XBW;
    u16* Blo = xblo + rg * 16 * XBW;
    u16* Chi = chi  + rg * 16 * CW;
    u16* Clo = clo  + rg * 16 * CW;

    const int blockPtBase = blockIdx.x * TPB * TILE_PTS;
    const int grow = lane >> 1;
    float2 gf[8]; float gwt[8];
    float gx0, gy0, gz0;

    {
        int gpt = blockPtBase + rg * 16 + grow;
        float px = pts[gpt * 3 + 0];
        float py = pts[gpt * 3 + 1];
        float pz = pts[gpt * 3 + 2];
        gx0 = (px + 1.0f) * 0.5f;
        gy0 = (py + 1.0f) * 0.5f;
        gz0 = (pz + 1.0f) * 0.5f;
#pragma unroll 1
        for (int c = 0; c < 6; c++) {
            int gl = 2 * c + (lane & 1);
            gather_issue(table, res.r[gl], gx0, gy0, gz0, gl, gf, gwt);
            gather_consume(Chi, Clo, grow, gl, gf, gwt);
        }
    }
    __syncwarp();

    for (int t = 0; t < TPB; t++) {
        const int base = blockPtBase + t * TILE_PTS;
        const bool g = (t + 1 < TPB);
        int gl = lane & 1;

        {   // L0: C -> XB
            float acc[8][4];
            run_layer<3, 8, 56, CW>(Chi, Clo, whi + WOFF_L0, wlo + WOFF_L0,
                                    bias + BOFF_L0, acc, lane);
            store_acts_gelu<8, XBW>(Bhi, Blo, acc, lane);
        }
        __syncwarp();
        if (g) {
            int gpt = base + TILE_PTS + rg * 16 + grow;
            float px = pts[gpt * 3 + 0];
            float py = pts[gpt * 3 + 1];
            float pz = pts[gpt * 3 + 2];
            gx0 = (px + 1.0f) * 0.5f;
            gy0 = (py + 1.0f) * 0.5f;
            gz0 = (pz + 1.0f) * 0.5f;
            gather_issue(table, res.r[gl], gx0, gy0, gz0, gl, gf, gwt);
        }

        {   // L1: XB -> XA
            float acc[8][4];
            run_layer<4, 8, 72, XBW>(Bhi, Blo, whi + WOFF_L1, wlo + WOFF_L1,
                                     bias + BOFF_L1, acc, lane);
            store_acts_gelu<8, XAW>(Ahi, Alo, acc, lane);
        }
        __syncwarp();
        if (g) {
            gather_consume(Chi, Clo, grow, gl, gf, gwt);
            gl += 2;
            gather_issue(table, res.r[gl], gx0, gy0, gz0, gl, gf, gwt);
        }

        {   // L2: XA -> XB
            float acc[8][4];
            run_layer<4, 8, 72, XAW>(Ahi, Alo, whi + WOFF_L2, wlo + WOFF_L2,
                                     bias + BOFF_L2, acc, lane);
            store_acts_gelu<8, XBW>(Bhi, Blo, acc, lane);
        }
        __syncwarp();
        if (g) {
            gather_consume(Chi, Clo, grow, gl, gf, gwt);
            gl += 2;
            gather_issue(table, res.r[gl], gx0, gy0, gz0, gl, gf, gwt);
        }

        {   // L3: XB -> XA + density
            float acc[9][4];
            run_layer<4, 9, 72, XBW>(Bhi, Blo, whi + WOFF_L3, wlo + WOFF_L3,
                                     bias + BOFF_L3, acc, lane);
#pragma unroll
            for (int nt = 0; nt < 9; nt++) {
#pragma unroll
                for (int j = 0; j < 4; j++) {
                    int col  = nt * 8 + 2 * qm + (j & 1);
                    int lrow = qr + ((j >> 1) ? 8 : 0);
                    float v = acc[nt][j];
                    if (col == 0) {
                        out[(size_t)3 * n + (base + rg * 16 + lrow)] =
                            softplus_f(v);
                    } else if (col <= 64) {
                        float ge = gelu_exact(v);
                        split_store1(Ahi + lrow * XAW + (col - 1),
                                     Alo + lrow * XAW + (col - 1), ge);
                    }
                }
            }
        }
        if (lane < 16) {
            int lrow = lane;
            int gpt = base + rg * 16 + lrow;
            float dx = dirs[gpt * 3 + 0];
            float dy = dirs[gpt * 3 + 1];
            float dz = dirs[gpt * 3 + 2];
            float sh[9];
            sh[0] = 0.28209479177387814f;
            sh[1] = -0.48860251190291987f * dy;
            sh[2] =  0.48860251190291987f * dz;
            sh[3] = -0.48860251190291987f * dx;
            sh[4] =  1.0925484305920792f  * dx * dy;
            sh[5] = -1.0925484305920792f  * dy * dz;
            sh[6] =  0.31539156525252005f * (3.0f * dz * dz - 1.0f);
            sh[7] = -1.0925484305920792f  * dx * dz;
            sh[8] =  0.5462742152960396f  * (dx * dx - dy * dy);
#pragma unroll
            for (int j = 0; j < 9; j++)
                split_store1(Ahi + lrow * XAW + 64 + j,
                             Alo + lrow * XAW + 64 + j, sh[j]);
        }
        __syncwarp();
        if (g) {
            gather_consume(Chi, Clo, grow, gl, gf, gwt);
            gl += 2;
            gather_issue(table, res.r[gl], gx0, gy0, gz0, gl, gf, gwt);
        }

        {   // R0: XA -> XB
            float acc[8][4];
            run_layer<5, 8, 88, XAW>(Ahi, Alo, whi + WOFF_R0, wlo + WOFF_R0,
                                     bias + BOFF_R0, acc, lane);
            store_acts_gelu<8, XBW>(Bhi, Blo, acc, lane);
        }
        __syncwarp();
        if (g) {
            gather_consume(Chi, Clo, grow, gl, gf, gwt);
            gl += 2;
            gather_issue(table, res.r[gl], gx0, gy0, gz0, gl, gf, gwt);
        }

        {   // R1: XB -> XA
            float acc[8][4];
            run_layer<4, 8, 72, XBW>(Bhi, Blo, whi + WOFF_R1, wlo + WOFF_R1,
                                     bias + BOFF_R1, acc, lane);
            store_acts_gelu<8, XAW>(Ahi, Alo, acc, lane);
        }
        __syncwarp();
        if (g) {
            gather_consume(Chi, Clo, grow, gl, gf, gwt);
            gl += 2;
            gather_issue(table, res.r[gl], gx0, gy0, gz0, gl, gf, gwt);
        }

        {   // R2: XA -> rgb
            float acc[1][4];
            run_layer<4, 1, 72, XAW>(Ahi, Alo, whi + WOFF_R2, wlo + WOFF_R2,
                                     bias + BOFF_R2, acc, lane);
            int pt0 = base + rg * 16 + qr;
            int pt1 = pt0 + 8;
            if (qm == 0) {
                out[pt0 * 3 + 0] = sigmoid_f(acc[0][0]);
                out[pt0 * 3 + 1] = sigmoid_f(acc[0][1]);
                out[pt1 * 3 + 0] = sigmoid_f(acc[0][2]);
                out[pt1 * 3 + 1] = sigmoid_f(acc[0][3]);
            } else if (qm == 1) {
                out[pt0 * 3 + 2] = sigmoid_f(acc[0][0]);
                out[pt1 * 3 + 2] = sigmoid_f(acc[0][2]);
            }
        }
        if (g)
            gather_consume(Chi, Clo, grow, gl, gf, gwt);
        __syncwarp();
    }
}

extern "C" void kernel_launch(void* const* d_in, const int* in_sizes, int n_in,
                              void* d_out, int out_size)
{
    const float* pts   = (const float*)d_in[0];
    const float* dirs  = (const float*)d_in[1];
    const float* table = (const float*)d_in[2];

    WPtrs prm;
    for (int a = 0; a < 14; a++) prm.w[a] = (const float*)d_in[3 + a];

    int n = in_sizes[0] / 3;

    ResArr res;
    double b = exp((log(2048.0) - log(16.0)) / 23.0);
    for (int l = 0; l < LVLS; l++)
        res.r[l] = (float)floor(16.0 * pow(b, (double)l));

    cudaFuncSetAttribute(nerf_tc_kernel,
                         cudaFuncAttributeMaxDynamicSharedMemorySize, SMEM_BYTES);

    int blocks = n / (TILE_PTS * TPB);   // 1024
    nerf_tc_kernel<<<blocks, NTHREADS, SMEM_BYTES>>>(
        pts, dirs, table, prm, res, (float*)d_out, n);
}

// round 7
// speedup vs baseline: 2.7572x; 2.0258x over previous
#include <cuda_runtime.h>
#include <cuda_bf16.h>
#include <math.h>
#include <stdint.h>

// ---------------------------------------------------------------------------
// Round 7: register-fragment layer chaining. Activations never touch smem:
// the D-fragment of layer i (after GELU + bf16 hi/lo split in registers) IS
// the A-fragment of layer i+1. Smem holds only weights + bias + enc plane
// (174 KB) -> 512 threads (16 warps/SM), every warp fully independent.
// R0's input-shift (fad[1:65]) is folded into shifted weight staging; SH
// terms are injected into R0's k-tile 4 per lane. Gather pipelined as R6.
// ---------------------------------------------------------------------------

#define LVLS 24
#define TSZ  (1u << 19)
#define P1   2654435761u
#define P2   805459861u

#define TILE_PTS  256          // 16 warps x 16 points
#define TPB       4
#define NTHREADS  512

#define CW   56                // enc plane stride (u16), conflict-free

// weight planes (u16 elems), transposed Wt[n][k]
#define WPLANE  28800
#define WOFF_L0 0              // 64 x 56 (K=48)
#define WOFF_L1 3584           // 64 x 72
#define WOFF_L2 8192           // 64 x 72
#define WOFF_L3 12800          // 72 x 72 (N 65->72)
#define WOFF_R0 17984          // 64 x 88 (K=80, staged shifted by 1)
#define WOFF_R1 23616          // 64 x 72
#define WOFF_R2 28224          //  8 x 72 (N 3->8)

#define BOFF_L0 0
#define BOFF_L1 64
#define BOFF_L2 128
#define BOFF_L3 192
#define BOFF_R0 264
#define BOFF_R1 328
#define BOFF_R2 392
#define BIAS_FLOATS 400

#define SO_WHI  0
#define SO_WLO  57600
#define SO_BIAS 115200
#define SO_CHI  116800                     // 256 x 56 u16 = 28672 B
#define SO_CLO  (SO_CHI + TILE_PTS * CW * 2)
#define SMEM_BYTES (SO_CLO + TILE_PTS * CW * 2)   // 174144

struct ResArr { float r[LVLS]; };
struct WPtrs  { const float* w[14]; };

typedef unsigned short u16;
typedef unsigned int   u32;

__device__ __forceinline__ float gelu_exact(float x) {
    return 0.5f * x * (1.0f + erff(x * 0.70710678118654752440f));
}
__device__ __forceinline__ float softplus_f(float x) {
    return fmaxf(x, 0.0f) + log1pf(expf(-fabsf(x)));
}
__device__ __forceinline__ float sigmoid_f(float x) {
    return 1.0f / (1.0f + expf(-x));
}

#define MMA_BF16(d, a0, a1, a2, a3, b0, b1)                                   \
    asm volatile(                                                             \
        "mma.sync.aligned.m16n8k16.row.col.f32.bf16.bf16.f32 "                \
        "{%0,%1,%2,%3}, {%4,%5,%6,%7}, {%8,%9}, {%0,%1,%2,%3};"               \
        : "+f"(d[0]), "+f"(d[1]), "+f"(d[2]), "+f"(d[3])                      \
        : "r"(a0), "r"(a1), "r"(a2), "r"(a3), "r"(b0), "r"(b1))

__device__ __forceinline__ void bf16_split(float v, u16& hi, u16& lo) {
    __nv_bfloat16 h = __float2bfloat16_rn(v);
    float r = v - __bfloat162float(h);
    __nv_bfloat16 l = __float2bfloat16_rn(r);
    hi = __bfloat16_as_ushort(h);
    lo = __bfloat16_as_ushort(l);
}

// pack two fp32 into bf16x2 hi and lo words
__device__ __forceinline__ void pack_split2(float v0, float v1,
                                            u32& h, u32& l) {
    u16 h0, l0, h1, l1;
    bf16_split(v0, h0, l0);
    bf16_split(v1, h1, l1);
    h = (u32)h0 | ((u32)h1 << 16);
    l = (u32)l0 | ((u32)l1 << 16);
}

__device__ __forceinline__ void split_store2(u16* phi, u16* plo,
                                             float v0, float v1) {
    u32 h, l;
    pack_split2(v0, v1, h, l);
    *(u32*)phi = h;
    *(u32*)plo = l;
}

// dense layer on register A-fragments. ah/al: KT*4 u32 each.
template<int KT, int NT, int KP>
__device__ __forceinline__ void run_layer_reg(const u32* __restrict__ ah,
                                              const u32* __restrict__ al,
                                              const u16* __restrict__ whi,
                                              const u16* __restrict__ wlo,
                                              const float* __restrict__ bias,
                                              float (&acc)[NT][4],
                                              int qr, int qm)
{
#pragma unroll
    for (int nt = 0; nt < NT; nt++) {
        float b0 = bias[nt * 8 + 2 * qm];
        float b1 = bias[nt * 8 + 2 * qm + 1];
        acc[nt][0] = b0; acc[nt][1] = b1;
        acc[nt][2] = b0; acc[nt][3] = b1;
    }
#pragma unroll
    for (int kt = 0; kt < KT; kt++) {
#pragma unroll
        for (int nt = 0; nt < NT; nt++) {
            const u16* pb  = whi + (nt * 8 + qr) * KP + 2 * qm + kt * 16;
            const u16* pbl = wlo + (nt * 8 + qr) * KP + 2 * qm + kt * 16;
            u32 bh0 = *(const u32*)(pb);
            u32 bh1 = *(const u32*)(pb + 8);
            u32 bl0 = *(const u32*)(pbl);
            u32 bl1 = *(const u32*)(pbl + 8);
            MMA_BF16(acc[nt], ah[4*kt], ah[4*kt+1], ah[4*kt+2], ah[4*kt+3],
                     bh0, bh1);
            MMA_BF16(acc[nt], ah[4*kt], ah[4*kt+1], ah[4*kt+2], ah[4*kt+3],
                     bl0, bl1);
            MMA_BF16(acc[nt], al[4*kt], al[4*kt+1], al[4*kt+2], al[4*kt+3],
                     bh0, bh1);
        }
    }
}

// D acc (2*KTN n-tiles) -> gelu -> A-fragments for next layer (KTN k-tiles)
template<int KTN>
__device__ __forceinline__ void frags_gelu(const float (*acc)[4],
                                           u32* ah, u32* al)
{
#pragma unroll
    for (int kt = 0; kt < KTN; kt++) {
        pack_split2(gelu_exact(acc[2*kt][0]),   gelu_exact(acc[2*kt][1]),
                    ah[4*kt+0], al[4*kt+0]);
        pack_split2(gelu_exact(acc[2*kt][2]),   gelu_exact(acc[2*kt][3]),
                    ah[4*kt+1], al[4*kt+1]);
        pack_split2(gelu_exact(acc[2*kt+1][0]), gelu_exact(acc[2*kt+1][1]),
                    ah[4*kt+2], al[4*kt+2]);
        pack_split2(gelu_exact(acc[2*kt+1][2]), gelu_exact(acc[2*kt+1][3]),
                    ah[4*kt+3], al[4*kt+3]);
    }
}

// ---- gather: issue LDGs + keep (wx,wy,wz); consume computes weights ----
struct GatherState {
    float2 f[8];
    float wx, wy, wz;
};

__device__ __forceinline__ void gather_issue(const float* __restrict__ table,
                                             float rl, float x0, float y0,
                                             float z0, int l, GatherState& gs)
{
    float posx = x0 * rl, posy = y0 * rl, posz = z0 * rl;
    float fx = floorf(posx), fy = floorf(posy), fz = floorf(posz);
    gs.wx = posx - fx; gs.wy = posy - fy; gs.wz = posz - fz;
    unsigned ux = (unsigned)fx, uy = (unsigned)fy, uz = (unsigned)fz;
    unsigned hX[2] = {ux, ux + 1u};
    unsigned hY[2] = {uy * P1, (uy + 1u) * P1};
    unsigned hZ[2] = {uz * P2, (uz + 1u) * P2};
    const float2* tb = (const float2*)table + (size_t)l * TSZ;
#pragma unroll
    for (int c = 0; c < 8; c++) {
        int bx = (c >> 2) & 1, by = (c >> 1) & 1, bz = c & 1;
        unsigned idx = (hX[bx] ^ hY[by] ^ hZ[bz]) & (TSZ - 1u);
        gs.f[c] = __ldg(tb + idx);
    }
}

__device__ __forceinline__ void gather_consume(u16* __restrict__ chi,
                                               u16* __restrict__ clo,
                                               int row, int l, GatherState& gs)
{
    float wX[2] = {1.0f - gs.wx, gs.wx};
    float wY[2] = {1.0f - gs.wy, gs.wy};
    float wZ[2] = {1.0f - gs.wz, gs.wz};
    float a0 = 0.0f, a1 = 0.0f;
#pragma unroll
    for (int c = 0; c < 8; c++) {
        int bx = (c >> 2) & 1, by = (c >> 1) & 1, bz = c & 1;
        float wt = wX[bx] * wY[by] * wZ[bz];
        a0 = fmaf(gs.f[c].x, wt, a0);
        a1 = fmaf(gs.f[c].y, wt, a1);
    }
    split_store2(chi + row * CW + 2 * l, clo + row * CW + 2 * l, a0, a1);
}

// ---- staging ----
__device__ void stage_w(const float* __restrict__ g, u16* hi, u16* lo,
                        int realK, int realN, int K, int NPAD, int KP, int tid)
{
    for (int idx = tid; idx < NPAD * K; idx += NTHREADS) {
        int nn = idx / K, kk = idx % K;
        float v = (kk < realK && nn < realN) ? g[kk * realN + nn] : 0.0f;
        u16 h, l;
        bf16_split(v, h, l);
        hi[nn * KP + kk] = h;
        lo[nn * KP + kk] = l;
    }
}
// rw0 staged shifted by one K-row: staged[k] = (1<=k<=73) ? rw0[k-1] : 0
__device__ void stage_w_shift(const float* __restrict__ g, u16* hi, u16* lo,
                              int tid)
{
    const int K = 80, KP = 88;
    for (int idx = tid; idx < 64 * K; idx += NTHREADS) {
        int nn = idx / K, kk = idx % K;
        float v = (kk >= 1 && kk <= 73) ? g[(kk - 1) * 64 + nn] : 0.0f;
        u16 h, l;
        bf16_split(v, h, l);
        hi[nn * KP + kk] = h;
        lo[nn * KP + kk] = l;
    }
}
__device__ void stage_b(const float* __restrict__ g, float* dst,
                        int realN, int NPAD, int tid)
{
    for (int i = tid; i < NPAD; i += NTHREADS)
        dst[i] = (i < realN) ? g[i] : 0.0f;
}

__global__ void __launch_bounds__(NTHREADS, 1)
nerf_tc_kernel(const float* __restrict__ pts,
               const float* __restrict__ dirs,
               const float* __restrict__ table,
               WPtrs prm, ResArr res,
               float* __restrict__ out, int n)
{
    extern __shared__ char smem[];
    u16*   whi  = (u16*)(smem + SO_WHI);
    u16*   wlo  = (u16*)(smem + SO_WLO);
    float* bias = (float*)(smem + SO_BIAS);
    u16*   chi  = (u16*)(smem + SO_CHI);
    u16*   clo  = (u16*)(smem + SO_CLO);

    const int tid  = threadIdx.x;
    const int warp = tid >> 5;
    const int lane = tid & 31;
    const int qr = lane >> 2, qm = lane & 3;
    const int rg = warp;                      // 16 rows per warp

    // ---- stage weights/biases once per block ----
    stage_w(prm.w[0],  whi + WOFF_L0, wlo + WOFF_L0, 48, 64, 48, 64, 56, tid);
    stage_w(prm.w[2],  whi + WOFF_L1, wlo + WOFF_L1, 64, 64, 64, 64, 72, tid);
    stage_w(prm.w[4],  whi + WOFF_L2, wlo + WOFF_L2, 64, 64, 64, 64, 72, tid);
    stage_w(prm.w[6],  whi + WOFF_L3, wlo + WOFF_L3, 64, 65, 64, 72, 72, tid);
    stage_w_shift(prm.w[8], whi + WOFF_R0, wlo + WOFF_R0, tid);
    stage_w(prm.w[10], whi + WOFF_R1, wlo + WOFF_R1, 64, 64, 64, 64, 72, tid);
    stage_w(prm.w[12], whi + WOFF_R2, wlo + WOFF_R2, 64,  3, 64,  8, 72, tid);
    stage_b(prm.w[1],  bias + BOFF_L0, 64, 64, tid);
    stage_b(prm.w[3],  bias + BOFF_L1, 64, 64, tid);
    stage_b(prm.w[5],  bias + BOFF_L2, 64, 64, tid);
    stage_b(prm.w[7],  bias + BOFF_L3, 65, 72, tid);
    stage_b(prm.w[9],  bias + BOFF_R0, 64, 64, tid);
    stage_b(prm.w[11], bias + BOFF_R1, 64, 64, tid);
    stage_b(prm.w[13], bias + BOFF_R2,  3,  8, tid);
    __syncthreads();

    u16* Chi = chi + rg * 16 * CW;
    u16* Clo = clo + rg * 16 * CW;

    const int blockPtBase = blockIdx.x * TPB * TILE_PTS;
    const int grow = lane >> 1;               // 2 lanes per point
    GatherState gs;
    float gx0, gy0, gz0;

    // ---- prologue: gather tile 0 ----
    {
        int gpt = blockPtBase + rg * 16 + grow;
        float px = pts[gpt * 3 + 0];
        float py = pts[gpt * 3 + 1];
        float pz = pts[gpt * 3 + 2];
        gx0 = (px + 1.0f) * 0.5f;
        gy0 = (py + 1.0f) * 0.5f;
        gz0 = (pz + 1.0f) * 0.5f;
#pragma unroll 1
        for (int c = 0; c < 6; c++) {
            int gl = 2 * c + (lane & 1);
            gather_issue(table, res.r[gl], gx0, gy0, gz0, gl, gs);
            gather_consume(Chi, Clo, grow, gl, gs);
        }
    }
    __syncwarp();

    for (int t = 0; t < TPB; t++) {
        const int base = blockPtBase + t * TILE_PTS;
        const bool g = (t + 1 < TPB);
        int gl = lane & 1;

        u32 ah[20], al[20];

        // ---- L0: A-frags from enc smem ----
        {
            const u16* pc  = Chi + qr * CW + 2 * qm;
            const u16* pcl = Clo + qr * CW + 2 * qm;
#pragma unroll
            for (int kt = 0; kt < 3; kt++) {
                ah[4*kt+0] = *(const u32*)(pc  + kt * 16);
                ah[4*kt+1] = *(const u32*)(pc  + kt * 16 + 8 * CW);
                ah[4*kt+2] = *(const u32*)(pc  + kt * 16 + 8);
                ah[4*kt+3] = *(const u32*)(pc  + kt * 16 + 8 * CW + 8);
                al[4*kt+0] = *(const u32*)(pcl + kt * 16);
                al[4*kt+1] = *(const u32*)(pcl + kt * 16 + 8 * CW);
                al[4*kt+2] = *(const u32*)(pcl + kt * 16 + 8);
                al[4*kt+3] = *(const u32*)(pcl + kt * 16 + 8 * CW + 8);
            }
        }
        float acc[8][4];
        run_layer_reg<3, 8, 56>(ah, al, whi + WOFF_L0, wlo + WOFF_L0,
                                bias + BOFF_L0, acc, qr, qm);
        __syncwarp();   // all lanes done reading C before gather overwrites
        if (g) {
            int gpt = base + TILE_PTS + rg * 16 + grow;
            float px = pts[gpt * 3 + 0];
            float py = pts[gpt * 3 + 1];
            float pz = pts[gpt * 3 + 2];
            gx0 = (px + 1.0f) * 0.5f;
            gy0 = (py + 1.0f) * 0.5f;
            gz0 = (pz + 1.0f) * 0.5f;
            gather_issue(table, res.r[gl], gx0, gy0, gz0, gl, gs);
        }

        // ---- L1 ----
        frags_gelu<4>(acc, ah, al);
        run_layer_reg<4, 8, 72>(ah, al, whi + WOFF_L1, wlo + WOFF_L1,
                                bias + BOFF_L1, acc, qr, qm);
        if (g) {
            gather_consume(Chi, Clo, grow, gl, gs);
            gl += 2;
            gather_issue(table, res.r[gl], gx0, gy0, gz0, gl, gs);
        }

        // ---- L2 ----
        frags_gelu<4>(acc, ah, al);
        run_layer_reg<4, 8, 72>(ah, al, whi + WOFF_L2, wlo + WOFF_L2,
                                bias + BOFF_L2, acc, qr, qm);
        if (g) {
            gather_consume(Chi, Clo, grow, gl, gs);
            gl += 2;
            gather_issue(table, res.r[gl], gx0, gy0, gz0, gl, gs);
        }

        // ---- L3 (N=72 padded from 65) ----
        frags_gelu<4>(acc, ah, al);
        float acc9[9][4];
        run_layer_reg<4, 9, 72>(ah, al, whi + WOFF_L3, wlo + WOFF_L3,
                                bias + BOFF_L3, acc9, qr, qm);
        // density = softplus(fad[0]) lives at col 64 of the shifted frame?
        // No: L3 staged unshifted -> col 0..64 = fad[0..64]. density = col 0?
        // L3 is NOT shifted: fad[c] at col c. density = fad[0] -> nt=0 col 0.
        if (qm == 0) {
            out[(size_t)3 * n + (base + rg * 16 + qr)]     = softplus_f(acc9[0][0]);
            out[(size_t)3 * n + (base + rg * 16 + qr + 8)] = softplus_f(acc9[0][2]);
        }
        // SH for rows qr and qr+8
        float shA[9], shB[9];
        {
            int gptA = base + rg * 16 + qr;
            int gptB = gptA + 8;
            float dxA = dirs[gptA * 3 + 0], dyA = dirs[gptA * 3 + 1],
                  dzA = dirs[gptA * 3 + 2];
            float dxB = dirs[gptB * 3 + 0], dyB = dirs[gptB * 3 + 1],
                  dzB = dirs[gptB * 3 + 2];
            shA[0] = 0.28209479177387814f;
            shA[1] = -0.48860251190291987f * dyA;
            shA[2] =  0.48860251190291987f * dzA;
            shA[3] = -0.48860251190291987f * dxA;
            shA[4] =  1.0925484305920792f  * dxA * dyA;
            shA[5] = -1.0925484305920792f  * dyA * dzA;
            shA[6] =  0.31539156525252005f * (3.0f * dzA * dzA - 1.0f);
            shA[7] = -1.0925484305920792f  * dxA * dzA;
            shA[8] =  0.5462742152960396f  * (dxA * dxA - dyA * dyA);
            shB[0] = 0.28209479177387814f;
            shB[1] = -0.48860251190291987f * dyB;
            shB[2] =  0.48860251190291987f * dzB;
            shB[3] = -0.48860251190291987f * dxB;
            shB[4] =  1.0925484305920792f  * dxB * dyB;
            shB[5] = -1.0925484305920792f  * dyB * dzB;
            shB[6] =  0.31539156525252005f * (3.0f * dzB * dzB - 1.0f);
            shB[7] = -1.0925484305920792f  * dxB * dzB;
            shB[8] =  0.5462742152960396f  * (dxB * dxB - dyB * dyB);
        }
        // R0 input y[k]: staged weights shifted by 1, so y[k]=gelu(fad[k-1])
        // must sit at k; equivalently A-frag col c = gelu(fad[c]) shifted via
        // weights. Direct mapping: y[c] = gelu(L3 col c) for c=0..64 (col 0 =
        // fad[0], weight row 0 is zero so its value is harmless),
        // y[65..73] = sh[0..8], y[74..79] = 0.
        frags_gelu<4>(acc9, ah, al);        // k-tiles 0..3 = cols 0..63
        {
            float e64A = gelu_exact(acc9[8][0]);   // col 64 (row qr)
            float e64B = gelu_exact(acc9[8][2]);   // col 64 (row qr+8)
            float v0A, v1A, v2A, v3A, v0B, v1B, v2B, v3B;
            if (qm == 0) {
                v0A = e64A;   v1A = shA[0]; v2A = shA[7]; v3A = shA[8];
                v0B = e64B;   v1B = shB[0]; v2B = shB[7]; v3B = shB[8];
            } else if (qm == 1) {
                v0A = shA[1]; v1A = shA[2]; v2A = 0.0f;   v3A = 0.0f;
                v0B = shB[1]; v1B = shB[2]; v2B = 0.0f;   v3B = 0.0f;
            } else if (qm == 2) {
                v0A = shA[3]; v1A = shA[4]; v2A = 0.0f;   v3A = 0.0f;
                v0B = shB[3]; v1B = shB[4]; v2B = 0.0f;   v3B = 0.0f;
            } else {
                v0A = shA[5]; v1A = shA[6]; v2A = 0.0f;   v3A = 0.0f;
                v0B = shB[5]; v1B = shB[6]; v2B = 0.0f;   v3B = 0.0f;
            }
            pack_split2(v0A, v1A, ah[16], al[16]);
            pack_split2(v0B, v1B, ah[17], al[17]);
            pack_split2(v2A, v3A, ah[18], al[18]);
            pack_split2(v2B, v3B, ah[19], al[19]);
        }
        if (g) {
            gather_consume(Chi, Clo, grow, gl, gs);
            gl += 2;
            gather_issue(table, res.r[gl], gx0, gy0, gz0, gl, gs);
        }

        // ---- R0 (K=80) ----
        run_layer_reg<5, 8, 88>(ah, al, whi + WOFF_R0, wlo + WOFF_R0,
                                bias + BOFF_R0, acc, qr, qm);
        if (g) {
            gather_consume(Chi, Clo, grow, gl, gs);
            gl += 2;
            gather_issue(table, res.r[gl], gx0, gy0, gz0, gl, gs);
        }

        // ---- R1 ----
        frags_gelu<4>(acc, ah, al);
        run_layer_reg<4, 8, 72>(ah, al, whi + WOFF_R1, wlo + WOFF_R1,
                                bias + BOFF_R1, acc, qr, qm);
        if (g) {
            gather_consume(Chi, Clo, grow, gl, gs);
            gl += 2;
            gather_issue(table, res.r[gl], gx0, gy0, gz0, gl, gs);
        }

        // ---- R2 ----
        frags_gelu<4>(acc, ah, al);
        {
            float acc1[1][4];
            run_layer_reg<4, 1, 72>(ah, al, whi + WOFF_R2, wlo + WOFF_R2,
                                    bias + BOFF_R2, acc1, qr, qm);
            int pt0 = base + rg * 16 + qr;
            int pt1 = pt0 + 8;
            if (qm == 0) {
                out[pt0 * 3 + 0] = sigmoid_f(acc1[0][0]);
                out[pt0 * 3 + 1] = sigmoid_f(acc1[0][1]);
                out[pt1 * 3 + 0] = sigmoid_f(acc1[0][2]);
                out[pt1 * 3 + 1] = sigmoid_f(acc1[0][3]);
            } else if (qm == 1) {
                out[pt0 * 3 + 2] = sigmoid_f(acc1[0][0]);
                out[pt1 * 3 + 2] = sigmoid_f(acc1[0][2]);
            }
        }
        if (g)
            gather_consume(Chi, Clo, grow, gl, gs);
        __syncwarp();
    }
}

extern "C" void kernel_launch(void* const* d_in, const int* in_sizes, int n_in,
                              void* d_out, int out_size)
{
    const float* pts   = (const float*)d_in[0];
    const float* dirs  = (const float*)d_in[1];
    const float* table = (const float*)d_in[2];

    WPtrs prm;
    for (int a = 0; a < 14; a++) prm.w[a] = (const float*)d_in[3 + a];

    int n = in_sizes[0] / 3;

    ResArr res;
    double b = exp((log(2048.0) - log(16.0)) / 23.0);
    for (int l = 0; l < LVLS; l++)
        res.r[l] = (float)floor(16.0 * pow(b, (double)l));

    cudaFuncSetAttribute(nerf_tc_kernel,
                         cudaFuncAttributeMaxDynamicSharedMemorySize, SMEM_BYTES);

    int blocks = n / (TILE_PTS * TPB);   // 512
    nerf_tc_kernel<<<blocks, NTHREADS, SMEM_BYTES>>>(
        pts, dirs, table, prm, res, (float*)d_out, n);
}